// round 7
// baseline (speedup 1.0000x reference)
#include <cuda_runtime.h>

#define NL 16
#define TSZ (1 << 19)
#define HMASK (TSZ - 1)
#define HP1 2654435761u
#define HP2 805459861u
#define BMAX 4096
#define SPB 48
#define NPTS (BMAX * SPB)
#define SROW 196            // smem row stride (192 samples + pad)
#define NT 384              // mlp threads per block

__constant__ float c_scal[NL] = {
    16.f, 22.f, 30.f, 42.f, 58.f, 80.f, 111.f, 153.f,
    212.f, 294.f, 406.f, 561.f, 776.f, 1072.f, 1482.f, 2048.f};

// MLP weights in constant memory (copied per launch; ~38.5 KB)
__constant__ float c_w1[2048], c_b1[64], c_w2[1024], c_b2[16];
__constant__ float c_h1[2048], c_hb1[64], c_h2[4096], c_hb2[64];
__constant__ float c_h3[192], c_hb3[3];

// scratch (device global; no runtime allocation)
__device__ float2 g_enc[16 * NPTS];  // level-major float2 features

// ---------------------------------------------------------------- kernel A
__global__ void __launch_bounds__(256) enc_kernel(
    const float* __restrict__ positions,
    const float* __restrict__ c2w,
    const float2* __restrict__ table)
{
    const int pt = blockIdx.x * 256 + threadIdx.x;
    const int b = pt / SPB;

    const float* cw = c2w + b * 12;
    float R00 = __ldg(cw+0), R01 = __ldg(cw+1), R02 = __ldg(cw+2),  t0 = __ldg(cw+3);
    float R10 = __ldg(cw+4), R11 = __ldg(cw+5), R12 = __ldg(cw+6),  t1 = __ldg(cw+7);
    float R20 = __ldg(cw+8), R21 = __ldg(cw+9), R22 = __ldg(cw+10), t2 = __ldg(cw+11);
    float p0 = positions[pt*3] - t0, p1 = positions[pt*3+1] - t1, p2 = positions[pt*3+2] - t2;
    float q0 = (R00*p0 + R10*p1 + R20*p2 + 1.f) * 0.5f;
    float q1 = (R01*p0 + R11*p1 + R21*p2 + 1.f) * 0.5f;
    float q2 = (R02*p0 + R12*p1 + R22*p2 + 1.f) * 0.5f;
    bool sel = (q0 > 0.f) && (q0 < 1.f) && (q1 > 0.f) && (q1 < 1.f) && (q2 > 0.f) && (q2 < 1.f);
    float m = sel ? 1.f : 0.f;
    q0 *= m; q1 *= m; q2 *= m;

#pragma unroll 2
    for (int l = 0; l < NL; l++) {
        float sc = c_scal[l];
        float sx = q0 * sc, sy = q1 * sc, sz = q2 * sc;
        float fxf = floorf(sx), fyf = floorf(sy), fzf = floorf(sz);
        float ox = sx - fxf, oy = sy - fyf, oz = sz - fzf;
        unsigned fx = (unsigned)fxf, fy = (unsigned)fyf, fz = (unsigned)fzf;
        unsigned cx = (unsigned)ceilf(sx), cy = (unsigned)ceilf(sy), cz = (unsigned)ceilf(sz);
        unsigned yc = cy * HP1, yf = fy * HP1;
        unsigned zc = cz * HP2, zf = fz * HP2;
        const float2* tl = table + (size_t)l * TSZ;
        float2 e0 = __ldg(tl + ((cx ^ yc ^ zc) & HMASK));
        float2 e1 = __ldg(tl + ((cx ^ yf ^ zc) & HMASK));
        float2 e2 = __ldg(tl + ((fx ^ yf ^ zc) & HMASK));
        float2 e3 = __ldg(tl + ((fx ^ yc ^ zc) & HMASK));
        float2 e4 = __ldg(tl + ((cx ^ yc ^ zf) & HMASK));
        float2 e5 = __ldg(tl + ((cx ^ yf ^ zf) & HMASK));
        float2 e6 = __ldg(tl + ((fx ^ yf ^ zf) & HMASK));
        float2 e7 = __ldg(tl + ((fx ^ yc ^ zf) & HMASK));
        float oxm = 1.f - ox, oym = 1.f - oy, ozm = 1.f - oz;
        float a03x = e0.x*ox + e3.x*oxm, a03y = e0.y*ox + e3.y*oxm;
        float a12x = e1.x*ox + e2.x*oxm, a12y = e1.y*ox + e2.y*oxm;
        float a56x = e5.x*ox + e6.x*oxm, a56y = e5.y*ox + e6.y*oxm;
        float a47x = e4.x*ox + e7.x*oxm, a47y = e4.y*ox + e7.y*oxm;
        float b0x = a03x*oy + a12x*oym, b0y = a03y*oy + a12y*oym;
        float b1x = a47x*oy + a56x*oym, b1y = a47y*oy + a56y*oym;
        g_enc[l * NPTS + pt] = make_float2(b0x*oz + b1x*ozm, b0y*oz + b1y*ozm);
    }
}

// ---------------------------------------------------------------- kernel B
// 384 threads: tm = tid%48 (4 samples each), tn = tid/48 (8 outputs each)
__global__ void __launch_bounds__(NT) mlp_kernel(
    const float* __restrict__ densities,
    const float* __restrict__ normals, const float* __restrict__ c2w,
    float* __restrict__ out)
{
    extern __shared__ float smem[];
    float* s1 = smem;                 // 64 x SROW
    float* s2 = smem + 64 * SROW;     // 64 x SROW
    __shared__ float sd16[4][16];
    __shared__ float sdc[4][64];

    const int tid = threadIdx.x;
    const int tm = tid % 48;
    const int tn = tid / 48;
    const int bb = blockIdx.x * 4;
    const int m0 = bb * SPB;

    // stage enc tile [32][192]
    for (int idx = tid; idx < 16 * 192; idx += NT) {
        int l = idx / 192, mm = idx % 192;
        float2 e = g_enc[l * NPTS + m0 + mm];
        s1[(2*l + 0) * SROW + mm] = e.x;
        s1[(2*l + 1) * SROW + mm] = e.y;
    }

    // per-batch SH16 (threads 0-3)
    if (tid < 4) {
        const int b = bb + tid;
        const float* cw = c2w + b * 12;
        float R00 = cw[0], R01 = cw[1], R02 = cw[2];
        float R10 = cw[4], R11 = cw[5], R12 = cw[6];
        float R20 = cw[8], R21 = cw[9], R22 = cw[10];
        float n0 = normals[b*3], n1 = normals[b*3+1], n2 = normals[b*3+2];
        float x = (R00*n0 + R10*n1 + R20*n2 + 1.f) * 0.5f;
        float y = (R01*n0 + R11*n1 + R21*n2 + 1.f) * 0.5f;
        float z = (R02*n0 + R12*n1 + R22*n2 + 1.f) * 0.5f;
        float xx = x*x, yy = y*y, zz = z*z;
        float* d16 = sd16[tid];
        d16[0]  = 0.28209479177387814f;
        d16[1]  = -0.48860251190291987f * y;
        d16[2]  = 0.48860251190291987f * z;
        d16[3]  = -0.48860251190291987f * x;
        d16[4]  = 1.0925484305920792f * x * y;
        d16[5]  = -1.0925484305920792f * y * z;
        d16[6]  = 0.94617469575756f * zz - 0.31539156525252f;
        d16[7]  = -1.0925484305920792f * x * z;
        d16[8]  = 0.5462742152960396f * (xx - yy);
        d16[9]  = 0.5900435899266435f * y * (3.0f * xx - yy);
        d16[10] = 2.890611442640554f * x * y * z;
        d16[11] = 0.4570457994644657f * y * (5.0f * zz - 1.0f);
        d16[12] = 0.37317633259011546f * z * (5.0f * zz - 3.0f);
        d16[13] = 0.4570457994644657f * x * (5.0f * zz - 1.0f);
        d16[14] = 1.445305721320277f * z * (xx - yy);
        d16[15] = 0.5900435899266435f * x * (xx - 3.0f * yy);
    }
    __syncthreads();

    // dc[g][j] = hb1[j] + d16[g] . h1[0:16, j]
    if (tid < 256) {
        int g = tid >> 6, j = tid & 63;
        float a = c_hb1[j];
#pragma unroll
        for (int i = 0; i < 16; i++) a = fmaf(sd16[g][i], c_h1[i * 64 + j], a);
        sdc[g][j] = a;
    }
    // sdc consumed in GEMM3, after ≥1 more __syncthreads

    float C[8][4];

    // ---- GEMM1: enc(32) -> hid(64), relu ----
    {
#pragma unroll
        for (int j = 0; j < 8; j++) {
            float bj = c_b1[tn * 8 + j];
#pragma unroll
            for (int i = 0; i < 4; i++) C[j][i] = bj;
        }
#pragma unroll 4
        for (int k = 0; k < 32; k++) {
            float4 a = *(const float4*)&s1[k * SROW + tm * 4];
            float A4[4] = {a.x, a.y, a.z, a.w};
#pragma unroll
            for (int j = 0; j < 8; j++) {
                float w = c_w1[k * 64 + tn * 8 + j];
#pragma unroll
                for (int i = 0; i < 4; i++) C[j][i] = fmaf(w, A4[i], C[j][i]);
            }
        }
#pragma unroll
        for (int j = 0; j < 8; j++) {
            int row = tn * 8 + j;
            *(float4*)&s2[row * SROW + tm * 4] = make_float4(
                fmaxf(C[j][0],0.f), fmaxf(C[j][1],0.f), fmaxf(C[j][2],0.f), fmaxf(C[j][3],0.f));
        }
    }
    __syncthreads();

    // ---- GEMM2: hid(64) -> geo(16), relu ----
    {
        float C2[2][4];
        float b0 = c_b2[tn * 2], b1v = c_b2[tn * 2 + 1];
#pragma unroll
        for (int i = 0; i < 4; i++) { C2[0][i] = b0; C2[1][i] = b1v; }
#pragma unroll 4
        for (int k = 0; k < 64; k++) {
            float4 a = *(const float4*)&s2[k * SROW + tm * 4];
            float A4[4] = {a.x, a.y, a.z, a.w};
            float w0 = c_w2[k * 16 + tn * 2], w1v = c_w2[k * 16 + tn * 2 + 1];
#pragma unroll
            for (int i = 0; i < 4; i++) {
                C2[0][i] = fmaf(w0, A4[i], C2[0][i]);
                C2[1][i] = fmaf(w1v, A4[i], C2[1][i]);
            }
        }
#pragma unroll
        for (int jj = 0; jj < 2; jj++) {
            int row = tn * 2 + jj;
            *(float4*)&s1[row * SROW + tm * 4] = make_float4(
                fmaxf(C2[jj][0],0.f), fmaxf(C2[jj][1],0.f), fmaxf(C2[jj][2],0.f), fmaxf(C2[jj][3],0.f));
        }
    }
    __syncthreads();

    // ---- GEMM3: geo(16) -> color hidden1 (64), init from per-batch dc, relu ----
    {
        const int gl = tm / 12;   // local batch (48 samples = 12 m-tiles of 4)
#pragma unroll
        for (int j = 0; j < 8; j++) {
            float dj = sdc[gl][tn * 8 + j];
#pragma unroll
            for (int i = 0; i < 4; i++) C[j][i] = dj;
        }
#pragma unroll 4
        for (int k = 0; k < 16; k++) {
            float4 a = *(const float4*)&s1[k * SROW + tm * 4];
            float A4[4] = {a.x, a.y, a.z, a.w};
#pragma unroll
            for (int j = 0; j < 8; j++) {
                float w = c_h1[(16 + k) * 64 + tn * 8 + j];
#pragma unroll
                for (int i = 0; i < 4; i++) C[j][i] = fmaf(w, A4[i], C[j][i]);
            }
        }
#pragma unroll
        for (int j = 0; j < 8; j++) {
            int row = tn * 8 + j;
            *(float4*)&s2[row * SROW + tm * 4] = make_float4(
                fmaxf(C[j][0],0.f), fmaxf(C[j][1],0.f), fmaxf(C[j][2],0.f), fmaxf(C[j][3],0.f));
        }
    }
    __syncthreads();

    // ---- GEMM4: hidden1(64) -> hidden2(64), +hb2, relu ----
    {
#pragma unroll
        for (int j = 0; j < 8; j++) {
            float bj = c_hb2[tn * 8 + j];
#pragma unroll
            for (int i = 0; i < 4; i++) C[j][i] = bj;
        }
#pragma unroll 4
        for (int k = 0; k < 64; k++) {
            float4 a = *(const float4*)&s2[k * SROW + tm * 4];
            float A4[4] = {a.x, a.y, a.z, a.w};
#pragma unroll
            for (int j = 0; j < 8; j++) {
                float w = c_h2[k * 64 + tn * 8 + j];
#pragma unroll
                for (int i = 0; i < 4; i++) C[j][i] = fmaf(w, A4[i], C[j][i]);
            }
        }
#pragma unroll
        for (int j = 0; j < 8; j++) {
            int row = tn * 8 + j;
            *(float4*)&s1[row * SROW + tm * 4] = make_float4(
                fmaxf(C[j][0],0.f), fmaxf(C[j][1],0.f), fmaxf(C[j][2],0.f), fmaxf(C[j][3],0.f));
        }
    }
    __syncthreads();

    // ---- final: hidden2 -> rgb(3), sigmoid; one sample per thread (tid<192) ----
    float* sden = s2;
    float* srgb = s2 + 192;
    if (tid < 192) {
        float r0 = c_hb3[0], r1 = c_hb3[1], r2 = c_hb3[2];
#pragma unroll 8
        for (int j = 0; j < 64; j++) {
            float t = s1[j * SROW + tid];
            r0 = fmaf(t, c_h3[j*3+0], r0);
            r1 = fmaf(t, c_h3[j*3+1], r1);
            r2 = fmaf(t, c_h3[j*3+2], r2);
        }
        r0 = 1.f / (1.f + expf(-r0));
        r1 = 1.f / (1.f + expf(-r1));
        r2 = 1.f / (1.f + expf(-r2));
        sden[tid] = densities[m0 + tid];
        srgb[tid*3+0] = r0; srgb[tid*3+1] = r1; srgb[tid*3+2] = r2;
    }
    __syncthreads();

    if (tid < 192 && (tid % SPB) == 0) {
        const int g = tid / SPB;
        const float* dn = &sden[g * SPB];
        float mx = -1e30f;
        for (int k = 0; k < SPB; k++) mx = fmaxf(mx, dn[k]);
        float sum = 0.f, a0 = 0.f, a1 = 0.f, a2 = 0.f;
        for (int k = 0; k < SPB; k++) {
            float w = expf(dn[k] - mx);
            sum += w;
            a0 = fmaf(w, srgb[(g*SPB+k)*3+0], a0);
            a1 = fmaf(w, srgb[(g*SPB+k)*3+1], a1);
            a2 = fmaf(w, srgb[(g*SPB+k)*3+2], a2);
        }
        float inv = 1.f / sum;
        const int b = bb + g;
        out[b*3+0] = a0 * inv;
        out[b*3+1] = a1 * inv;
        out[b*3+2] = a2 * inv;
    }
}

// ---------------------------------------------------------------- launch
extern "C" void kernel_launch(void* const* d_in, const int* in_sizes, int n_in,
                              void* d_out, int out_size) {
    const float*  positions = (const float*)d_in[0];
    const float*  densities = (const float*)d_in[1];
    const float*  normals   = (const float*)d_in[2];
    const float*  c2w       = (const float*)d_in[3];
    const float2* table     = (const float2*)d_in[4];
    float* out = (float*)d_out;

    const int B = in_sizes[2] / 3;        // 4096
    const int npts = B * SPB;             // 196608
    const int smem_b = 2 * 64 * SROW * (int)sizeof(float);  // 100352 B

    cudaFuncSetAttribute(mlp_kernel, cudaFuncAttributeMaxDynamicSharedMemorySize, smem_b);

    // weights into constant memory (async D2D memcpys; graph-capturable)
    cudaMemcpyToSymbolAsync(c_w1,  d_in[5],  2048 * sizeof(float), 0, cudaMemcpyDeviceToDevice, 0);
    cudaMemcpyToSymbolAsync(c_b1,  d_in[6],    64 * sizeof(float), 0, cudaMemcpyDeviceToDevice, 0);
    cudaMemcpyToSymbolAsync(c_w2,  d_in[7],  1024 * sizeof(float), 0, cudaMemcpyDeviceToDevice, 0);
    cudaMemcpyToSymbolAsync(c_b2,  d_in[8],    16 * sizeof(float), 0, cudaMemcpyDeviceToDevice, 0);
    cudaMemcpyToSymbolAsync(c_h1,  d_in[9],  2048 * sizeof(float), 0, cudaMemcpyDeviceToDevice, 0);
    cudaMemcpyToSymbolAsync(c_hb1, d_in[10],   64 * sizeof(float), 0, cudaMemcpyDeviceToDevice, 0);
    cudaMemcpyToSymbolAsync(c_h2,  d_in[11], 4096 * sizeof(float), 0, cudaMemcpyDeviceToDevice, 0);
    cudaMemcpyToSymbolAsync(c_hb2, d_in[12],   64 * sizeof(float), 0, cudaMemcpyDeviceToDevice, 0);
    cudaMemcpyToSymbolAsync(c_h3,  d_in[13],  192 * sizeof(float), 0, cudaMemcpyDeviceToDevice, 0);
    cudaMemcpyToSymbolAsync(c_hb3, d_in[14],    3 * sizeof(float), 0, cudaMemcpyDeviceToDevice, 0);

    enc_kernel<<<npts / 256, 256>>>(positions, c2w, table);
    mlp_kernel<<<B / 4, NT, smem_b>>>(densities, normals, c2w, out);
}

// round 8
// speedup vs baseline: 1.1488x; 1.1488x over previous
#include <cuda_runtime.h>

#define NL 16
#define TSZ (1 << 19)
#define HMASK (TSZ - 1)
#define HP1 2654435761u
#define HP2 805459861u
#define BMAX 4096
#define SPB 48
#define NPTS (BMAX * SPB)
#define SROW 196            // smem row stride (192 samples + pad)
#define NT 384              // mlp threads per block

__constant__ float c_scal[NL] = {
    16.f, 22.f, 30.f, 42.f, 58.f, 80.f, 111.f, 153.f,
    212.f, 294.f, 406.f, 561.f, 776.f, 1072.f, 1482.f, 2048.f};

// scratch (device global; no runtime allocation)
__device__ float2 g_enc[16 * NPTS];  // level-major float2 features

// ---------------------------------------------------------------- kernel A
__global__ void __launch_bounds__(256) enc_kernel(
    const float* __restrict__ positions,
    const float* __restrict__ c2w,
    const float2* __restrict__ table)
{
    const int pt = blockIdx.x * 256 + threadIdx.x;
    const int b = pt / SPB;

    const float* cw = c2w + b * 12;
    float R00 = __ldg(cw+0), R01 = __ldg(cw+1), R02 = __ldg(cw+2),  t0 = __ldg(cw+3);
    float R10 = __ldg(cw+4), R11 = __ldg(cw+5), R12 = __ldg(cw+6),  t1 = __ldg(cw+7);
    float R20 = __ldg(cw+8), R21 = __ldg(cw+9), R22 = __ldg(cw+10), t2 = __ldg(cw+11);
    float p0 = positions[pt*3] - t0, p1 = positions[pt*3+1] - t1, p2 = positions[pt*3+2] - t2;
    float q0 = (R00*p0 + R10*p1 + R20*p2 + 1.f) * 0.5f;
    float q1 = (R01*p0 + R11*p1 + R21*p2 + 1.f) * 0.5f;
    float q2 = (R02*p0 + R12*p1 + R22*p2 + 1.f) * 0.5f;
    bool sel = (q0 > 0.f) && (q0 < 1.f) && (q1 > 0.f) && (q1 < 1.f) && (q2 > 0.f) && (q2 < 1.f);
    float m = sel ? 1.f : 0.f;
    q0 *= m; q1 *= m; q2 *= m;

#pragma unroll 2
    for (int l = 0; l < NL; l++) {
        float sc = c_scal[l];
        float sx = q0 * sc, sy = q1 * sc, sz = q2 * sc;
        float fxf = floorf(sx), fyf = floorf(sy), fzf = floorf(sz);
        float ox = sx - fxf, oy = sy - fyf, oz = sz - fzf;
        unsigned fx = (unsigned)fxf, fy = (unsigned)fyf, fz = (unsigned)fzf;
        unsigned cx = (unsigned)ceilf(sx), cy = (unsigned)ceilf(sy), cz = (unsigned)ceilf(sz);
        unsigned yc = cy * HP1, yf = fy * HP1;
        unsigned zc = cz * HP2, zf = fz * HP2;
        const float2* tl = table + (size_t)l * TSZ;
        float2 e0 = __ldg(tl + ((cx ^ yc ^ zc) & HMASK));
        float2 e1 = __ldg(tl + ((cx ^ yf ^ zc) & HMASK));
        float2 e2 = __ldg(tl + ((fx ^ yf ^ zc) & HMASK));
        float2 e3 = __ldg(tl + ((fx ^ yc ^ zc) & HMASK));
        float2 e4 = __ldg(tl + ((cx ^ yc ^ zf) & HMASK));
        float2 e5 = __ldg(tl + ((cx ^ yf ^ zf) & HMASK));
        float2 e6 = __ldg(tl + ((fx ^ yf ^ zf) & HMASK));
        float2 e7 = __ldg(tl + ((fx ^ yc ^ zf) & HMASK));
        float oxm = 1.f - ox, oym = 1.f - oy, ozm = 1.f - oz;
        float a03x = e0.x*ox + e3.x*oxm, a03y = e0.y*ox + e3.y*oxm;
        float a12x = e1.x*ox + e2.x*oxm, a12y = e1.y*ox + e2.y*oxm;
        float a56x = e5.x*ox + e6.x*oxm, a56y = e5.y*ox + e6.y*oxm;
        float a47x = e4.x*ox + e7.x*oxm, a47y = e4.y*ox + e7.y*oxm;
        float b0x = a03x*oy + a12x*oym, b0y = a03y*oy + a12y*oym;
        float b1x = a47x*oy + a56x*oym, b1y = a47y*oy + a56y*oym;
        g_enc[l * NPTS + pt] = make_float2(b0x*oz + b1x*ozm, b0y*oz + b1y*ozm);
    }
}

// ---------------------------------------------------------------- kernel B
// 384 threads: tm = tid%48 (4 samples each), tn = tid/48 (8 outputs each)
__global__ void __launch_bounds__(NT) mlp_kernel(
    const float* __restrict__ densities,
    const float* __restrict__ normals, const float* __restrict__ c2w,
    const float* __restrict__ w1g, const float* __restrict__ b1g,
    const float* __restrict__ w2g, const float* __restrict__ b2g,
    const float* __restrict__ h1g, const float* __restrict__ hb1g,
    const float* __restrict__ h2g, const float* __restrict__ hb2g,
    const float* __restrict__ h3g, const float* __restrict__ hb3g,
    float* __restrict__ out)
{
    extern __shared__ float smem[];
    float* s1 = smem;                 // 64 x SROW
    float* s2 = smem + 64 * SROW;     // 64 x SROW
    __shared__ float sd16[4][16];
    __shared__ float sdc[4][64];

    const int tid = threadIdx.x;
    const int tm = tid % 48;
    const int tn = tid / 48;
    const int bb = blockIdx.x * 4;
    const int m0 = bb * SPB;

    // stage enc tile [32][192]
    for (int idx = tid; idx < 16 * 192; idx += NT) {
        int l = idx / 192, mm = idx % 192;
        float2 e = g_enc[l * NPTS + m0 + mm];
        s1[(2*l + 0) * SROW + mm] = e.x;
        s1[(2*l + 1) * SROW + mm] = e.y;
    }

    // per-batch SH16 (threads 0-3)
    if (tid < 4) {
        const int b = bb + tid;
        const float* cw = c2w + b * 12;
        float R00 = cw[0], R01 = cw[1], R02 = cw[2];
        float R10 = cw[4], R11 = cw[5], R12 = cw[6];
        float R20 = cw[8], R21 = cw[9], R22 = cw[10];
        float n0 = normals[b*3], n1 = normals[b*3+1], n2 = normals[b*3+2];
        float x = (R00*n0 + R10*n1 + R20*n2 + 1.f) * 0.5f;
        float y = (R01*n0 + R11*n1 + R21*n2 + 1.f) * 0.5f;
        float z = (R02*n0 + R12*n1 + R22*n2 + 1.f) * 0.5f;
        float xx = x*x, yy = y*y, zz = z*z;
        float* d16 = sd16[tid];
        d16[0]  = 0.28209479177387814f;
        d16[1]  = -0.48860251190291987f * y;
        d16[2]  = 0.48860251190291987f * z;
        d16[3]  = -0.48860251190291987f * x;
        d16[4]  = 1.0925484305920792f * x * y;
        d16[5]  = -1.0925484305920792f * y * z;
        d16[6]  = 0.94617469575756f * zz - 0.31539156525252f;
        d16[7]  = -1.0925484305920792f * x * z;
        d16[8]  = 0.5462742152960396f * (xx - yy);
        d16[9]  = 0.5900435899266435f * y * (3.0f * xx - yy);
        d16[10] = 2.890611442640554f * x * y * z;
        d16[11] = 0.4570457994644657f * y * (5.0f * zz - 1.0f);
        d16[12] = 0.37317633259011546f * z * (5.0f * zz - 3.0f);
        d16[13] = 0.4570457994644657f * x * (5.0f * zz - 1.0f);
        d16[14] = 1.445305721320277f * z * (xx - yy);
        d16[15] = 0.5900435899266435f * x * (xx - 3.0f * yy);
    }
    __syncthreads();

    // dc[g][j] = hb1[j] + d16[g] . h1[0:16, j]
    if (tid < 256) {
        int g = tid >> 6, j = tid & 63;
        float a = __ldg(&hb1g[j]);
#pragma unroll
        for (int i = 0; i < 16; i++) a = fmaf(sd16[g][i], __ldg(&h1g[i * 64 + j]), a);
        sdc[g][j] = a;
    }
    // sdc consumed in GEMM3, after ≥1 more __syncthreads

    float C[8][4];

    // ---- GEMM1: enc(32) -> hid(64), relu ----
    {
        float4 bv0 = __ldg((const float4*)&b1g[tn * 8]);
        float4 bv1 = __ldg((const float4*)&b1g[tn * 8 + 4]);
        float bj[8] = {bv0.x, bv0.y, bv0.z, bv0.w, bv1.x, bv1.y, bv1.z, bv1.w};
#pragma unroll
        for (int j = 0; j < 8; j++)
#pragma unroll
            for (int i = 0; i < 4; i++) C[j][i] = bj[j];
#pragma unroll 4
        for (int k = 0; k < 32; k++) {
            float4 a = *(const float4*)&s1[k * SROW + tm * 4];
            float A4[4] = {a.x, a.y, a.z, a.w};
            float4 w0 = __ldg((const float4*)&w1g[k * 64 + tn * 8]);
            float4 w1v = __ldg((const float4*)&w1g[k * 64 + tn * 8 + 4]);
            float W8[8] = {w0.x,w0.y,w0.z,w0.w,w1v.x,w1v.y,w1v.z,w1v.w};
#pragma unroll
            for (int j = 0; j < 8; j++)
#pragma unroll
                for (int i = 0; i < 4; i++) C[j][i] = fmaf(W8[j], A4[i], C[j][i]);
        }
#pragma unroll
        for (int j = 0; j < 8; j++) {
            int row = tn * 8 + j;
            *(float4*)&s2[row * SROW + tm * 4] = make_float4(
                fmaxf(C[j][0],0.f), fmaxf(C[j][1],0.f), fmaxf(C[j][2],0.f), fmaxf(C[j][3],0.f));
        }
    }
    __syncthreads();

    // ---- GEMM2: hid(64) -> geo(16), relu ----
    {
        float C2[2][4];
        float2 bv = __ldg((const float2*)&b2g[tn * 2]);
#pragma unroll
        for (int i = 0; i < 4; i++) { C2[0][i] = bv.x; C2[1][i] = bv.y; }
#pragma unroll 4
        for (int k = 0; k < 64; k++) {
            float4 a = *(const float4*)&s2[k * SROW + tm * 4];
            float A4[4] = {a.x, a.y, a.z, a.w};
            float2 w = __ldg((const float2*)&w2g[k * 16 + tn * 2]);
#pragma unroll
            for (int i = 0; i < 4; i++) {
                C2[0][i] = fmaf(w.x, A4[i], C2[0][i]);
                C2[1][i] = fmaf(w.y, A4[i], C2[1][i]);
            }
        }
#pragma unroll
        for (int jj = 0; jj < 2; jj++) {
            int row = tn * 2 + jj;
            *(float4*)&s1[row * SROW + tm * 4] = make_float4(
                fmaxf(C2[jj][0],0.f), fmaxf(C2[jj][1],0.f), fmaxf(C2[jj][2],0.f), fmaxf(C2[jj][3],0.f));
        }
    }
    __syncthreads();

    // ---- GEMM3: geo(16) -> color hidden1 (64), init from per-batch dc, relu ----
    {
        const int gl = tm / 12;   // local batch (48 samples = 12 m-tiles of 4)
#pragma unroll
        for (int j = 0; j < 8; j++) {
            float dj = sdc[gl][tn * 8 + j];
#pragma unroll
            for (int i = 0; i < 4; i++) C[j][i] = dj;
        }
#pragma unroll 4
        for (int k = 0; k < 16; k++) {
            float4 a = *(const float4*)&s1[k * SROW + tm * 4];
            float A4[4] = {a.x, a.y, a.z, a.w};
            float4 w0 = __ldg((const float4*)&h1g[(16 + k) * 64 + tn * 8]);
            float4 w1v = __ldg((const float4*)&h1g[(16 + k) * 64 + tn * 8 + 4]);
            float W8[8] = {w0.x,w0.y,w0.z,w0.w,w1v.x,w1v.y,w1v.z,w1v.w};
#pragma unroll
            for (int j = 0; j < 8; j++)
#pragma unroll
                for (int i = 0; i < 4; i++) C[j][i] = fmaf(W8[j], A4[i], C[j][i]);
        }
#pragma unroll
        for (int j = 0; j < 8; j++) {
            int row = tn * 8 + j;
            *(float4*)&s2[row * SROW + tm * 4] = make_float4(
                fmaxf(C[j][0],0.f), fmaxf(C[j][1],0.f), fmaxf(C[j][2],0.f), fmaxf(C[j][3],0.f));
        }
    }
    __syncthreads();

    // ---- GEMM4: hidden1(64) -> hidden2(64), +hb2, relu ----
    {
        float4 bv0 = __ldg((const float4*)&hb2g[tn * 8]);
        float4 bv1 = __ldg((const float4*)&hb2g[tn * 8 + 4]);
        float bj[8] = {bv0.x, bv0.y, bv0.z, bv0.w, bv1.x, bv1.y, bv1.z, bv1.w};
#pragma unroll
        for (int j = 0; j < 8; j++)
#pragma unroll
            for (int i = 0; i < 4; i++) C[j][i] = bj[j];
#pragma unroll 4
        for (int k = 0; k < 64; k++) {
            float4 a = *(const float4*)&s2[k * SROW + tm * 4];
            float A4[4] = {a.x, a.y, a.z, a.w};
            float4 w0 = __ldg((const float4*)&h2g[k * 64 + tn * 8]);
            float4 w1v = __ldg((const float4*)&h2g[k * 64 + tn * 8 + 4]);
            float W8[8] = {w0.x,w0.y,w0.z,w0.w,w1v.x,w1v.y,w1v.z,w1v.w};
#pragma unroll
            for (int j = 0; j < 8; j++)
#pragma unroll
                for (int i = 0; i < 4; i++) C[j][i] = fmaf(W8[j], A4[i], C[j][i]);
        }
#pragma unroll
        for (int j = 0; j < 8; j++) {
            int row = tn * 8 + j;
            *(float4*)&s1[row * SROW + tm * 4] = make_float4(
                fmaxf(C[j][0],0.f), fmaxf(C[j][1],0.f), fmaxf(C[j][2],0.f), fmaxf(C[j][3],0.f));
        }
    }
    __syncthreads();

    // ---- final: hidden2 -> rgb(3), sigmoid; one sample per thread (tid<192) ----
    float* sden = s2;
    float* srgb = s2 + 192;
    if (tid < 192) {
        float r0 = __ldg(&hb3g[0]), r1 = __ldg(&hb3g[1]), r2 = __ldg(&hb3g[2]);
#pragma unroll 8
        for (int j = 0; j < 64; j++) {
            float t = s1[j * SROW + tid];
            r0 = fmaf(t, __ldg(&h3g[j*3+0]), r0);
            r1 = fmaf(t, __ldg(&h3g[j*3+1]), r1);
            r2 = fmaf(t, __ldg(&h3g[j*3+2]), r2);
        }
        r0 = 1.f / (1.f + expf(-r0));
        r1 = 1.f / (1.f + expf(-r1));
        r2 = 1.f / (1.f + expf(-r2));
        sden[tid] = densities[m0 + tid];
        srgb[tid*3+0] = r0; srgb[tid*3+1] = r1; srgb[tid*3+2] = r2;
    }
    __syncthreads();

    if (tid < 192 && (tid % SPB) == 0) {
        const int g = tid / SPB;
        const float* dn = &sden[g * SPB];
        float mx = -1e30f;
        for (int k = 0; k < SPB; k++) mx = fmaxf(mx, dn[k]);
        float sum = 0.f, a0 = 0.f, a1 = 0.f, a2 = 0.f;
        for (int k = 0; k < SPB; k++) {
            float w = expf(dn[k] - mx);
            sum += w;
            a0 = fmaf(w, srgb[(g*SPB+k)*3+0], a0);
            a1 = fmaf(w, srgb[(g*SPB+k)*3+1], a1);
            a2 = fmaf(w, srgb[(g*SPB+k)*3+2], a2);
        }
        float inv = 1.f / sum;
        const int b = bb + g;
        out[b*3+0] = a0 * inv;
        out[b*3+1] = a1 * inv;
        out[b*3+2] = a2 * inv;
    }
}

// ---------------------------------------------------------------- launch
extern "C" void kernel_launch(void* const* d_in, const int* in_sizes, int n_in,
                              void* d_out, int out_size) {
    const float*  positions = (const float*)d_in[0];
    const float*  densities = (const float*)d_in[1];
    const float*  normals   = (const float*)d_in[2];
    const float*  c2w       = (const float*)d_in[3];
    const float2* table     = (const float2*)d_in[4];
    const float*  w1  = (const float*)d_in[5];
    const float*  b1  = (const float*)d_in[6];
    const float*  w2  = (const float*)d_in[7];
    const float*  b2  = (const float*)d_in[8];
    const float*  h1  = (const float*)d_in[9];
    const float*  hb1 = (const float*)d_in[10];
    const float*  h2  = (const float*)d_in[11];
    const float*  hb2 = (const float*)d_in[12];
    const float*  h3  = (const float*)d_in[13];
    const float*  hb3 = (const float*)d_in[14];
    float* out = (float*)d_out;

    const int B = in_sizes[2] / 3;        // 4096
    const int npts = B * SPB;             // 196608
    const int smem_b = 2 * 64 * SROW * (int)sizeof(float);  // 100352 B

    cudaFuncSetAttribute(mlp_kernel, cudaFuncAttributeMaxDynamicSharedMemorySize, smem_b);

    enc_kernel<<<npts / 256, 256>>>(positions, c2w, table);
    mlp_kernel<<<B / 4, NT, smem_b>>>(densities, normals, c2w,
                                      w1, b1, w2, b2, h1, hb1, h2, hb2, h3, hb3, out);
}

// round 10
// speedup vs baseline: 1.4900x; 1.2970x over previous
#include <cuda_runtime.h>

#define NL 16
#define TSZ (1 << 19)
#define HMASK (TSZ - 1)
#define HP1 2654435761u
#define HP2 805459861u
#define BMAX 4096
#define SPB 48
#define NPTS (BMAX * SPB)
#define SROW 196            // multiple of 4 (float4 alignment); stride-4 banks conflict-free loads

__constant__ float c_scal[NL] = {
    16.f, 22.f, 30.f, 42.f, 58.f, 80.f, 111.f, 153.f,
    212.f, 294.f, 406.f, 561.f, 776.f, 1072.f, 1482.f, 2048.f};

// scratch (device global; no runtime allocation)
__device__ float2 g_enc[16 * NPTS];  // level-major float2 features

// ---------------------------------------------------------------- kernel A
__global__ void __launch_bounds__(256) enc_kernel(
    const float* __restrict__ positions,
    const float* __restrict__ c2w,
    const float2* __restrict__ table)
{
    const int pt = blockIdx.x * 256 + threadIdx.x;
    const int b = pt / SPB;

    const float* cw = c2w + b * 12;
    float R00 = __ldg(cw+0), R01 = __ldg(cw+1), R02 = __ldg(cw+2),  t0 = __ldg(cw+3);
    float R10 = __ldg(cw+4), R11 = __ldg(cw+5), R12 = __ldg(cw+6),  t1 = __ldg(cw+7);
    float R20 = __ldg(cw+8), R21 = __ldg(cw+9), R22 = __ldg(cw+10), t2 = __ldg(cw+11);
    float p0 = positions[pt*3] - t0, p1 = positions[pt*3+1] - t1, p2 = positions[pt*3+2] - t2;
    float q0 = (R00*p0 + R10*p1 + R20*p2 + 1.f) * 0.5f;
    float q1 = (R01*p0 + R11*p1 + R21*p2 + 1.f) * 0.5f;
    float q2 = (R02*p0 + R12*p1 + R22*p2 + 1.f) * 0.5f;
    bool sel = (q0 > 0.f) && (q0 < 1.f) && (q1 > 0.f) && (q1 < 1.f) && (q2 > 0.f) && (q2 < 1.f);
    float m = sel ? 1.f : 0.f;
    q0 *= m; q1 *= m; q2 *= m;

#pragma unroll 2
    for (int l = 0; l < NL; l++) {
        float sc = c_scal[l];
        float sx = q0 * sc, sy = q1 * sc, sz = q2 * sc;
        float fxf = floorf(sx), fyf = floorf(sy), fzf = floorf(sz);
        float ox = sx - fxf, oy = sy - fyf, oz = sz - fzf;
        unsigned fx = (unsigned)fxf, fy = (unsigned)fyf, fz = (unsigned)fzf;
        unsigned cx = (unsigned)ceilf(sx), cy = (unsigned)ceilf(sy), cz = (unsigned)ceilf(sz);
        unsigned yc = cy * HP1, yf = fy * HP1;
        unsigned zc = cz * HP2, zf = fz * HP2;
        const float2* tl = table + (size_t)l * TSZ;
        float2 e0 = __ldg(tl + ((cx ^ yc ^ zc) & HMASK));
        float2 e1 = __ldg(tl + ((cx ^ yf ^ zc) & HMASK));
        float2 e2 = __ldg(tl + ((fx ^ yf ^ zc) & HMASK));
        float2 e3 = __ldg(tl + ((fx ^ yc ^ zc) & HMASK));
        float2 e4 = __ldg(tl + ((cx ^ yc ^ zf) & HMASK));
        float2 e5 = __ldg(tl + ((cx ^ yf ^ zf) & HMASK));
        float2 e6 = __ldg(tl + ((fx ^ yf ^ zf) & HMASK));
        float2 e7 = __ldg(tl + ((fx ^ yc ^ zf) & HMASK));
        float oxm = 1.f - ox, oym = 1.f - oy, ozm = 1.f - oz;
        float a03x = e0.x*ox + e3.x*oxm, a03y = e0.y*ox + e3.y*oxm;
        float a12x = e1.x*ox + e2.x*oxm, a12y = e1.y*ox + e2.y*oxm;
        float a56x = e5.x*ox + e6.x*oxm, a56y = e5.y*ox + e6.y*oxm;
        float a47x = e4.x*ox + e7.x*oxm, a47y = e4.y*ox + e7.y*oxm;
        float b0x = a03x*oy + a12x*oym, b0y = a03y*oy + a12y*oym;
        float b1x = a47x*oy + a56x*oym, b1y = a47y*oy + a56y*oym;
        g_enc[l * NPTS + pt] = make_float2(b0x*oz + b1x*ozm, b0y*oz + b1y*ozm);
    }
}

// ---------------------------------------------------------------- kernel B
// 192 threads; warp w exclusively owns sample-columns 32w..32w+31.
// tm = w*4 + (lane&3)  (m-tile, 8 samples), tn = lane>>2 (8 outputs).
__global__ void __launch_bounds__(192, 3) mlp_kernel(
    const float* __restrict__ densities,
    const float* __restrict__ normals, const float* __restrict__ c2w,
    const float* __restrict__ w1g, const float* __restrict__ b1g,
    const float* __restrict__ w2g, const float* __restrict__ b2g,
    const float* __restrict__ h1g, const float* __restrict__ hb1g,
    const float* __restrict__ h2g, const float* __restrict__ hb2g,
    const float* __restrict__ h3g, const float* __restrict__ hb3g,
    float* __restrict__ out)
{
    extern __shared__ float s1[];     // 64 x SROW, in-place buffer
    __shared__ float sdc[4][64];
    __shared__ float sden[192];
    __shared__ float srgb[192][3];

    const int tid = threadIdx.x;
    const int lane = tid & 31;
    const int wrp = tid >> 5;
    const int tm = wrp * 4 + (lane & 3);  // 0..23
    const int tn = lane >> 2;             // 0..7
    const int bb = blockIdx.x * 4;
    const int m0 = bb * SPB;

    // ---- prologue: dc[g][j] = hb1[j] + SH16(batch g) . h1[0:16, j] ----
    for (int idx = tid; idx < 256; idx += 192) {
        int g = idx >> 6, j = idx & 63;
        const int b = bb + g;
        const float* cw = c2w + b * 12;
        float R00 = cw[0], R01 = cw[1], R02 = cw[2];
        float R10 = cw[4], R11 = cw[5], R12 = cw[6];
        float R20 = cw[8], R21 = cw[9], R22 = cw[10];
        float n0 = normals[b*3], n1 = normals[b*3+1], n2 = normals[b*3+2];
        float x = (R00*n0 + R10*n1 + R20*n2 + 1.f) * 0.5f;
        float y = (R01*n0 + R11*n1 + R21*n2 + 1.f) * 0.5f;
        float z = (R02*n0 + R12*n1 + R22*n2 + 1.f) * 0.5f;
        float xx = x*x, yy = y*y, zz = z*z;
        float d16[16];
        d16[0]  = 0.28209479177387814f;
        d16[1]  = -0.48860251190291987f * y;
        d16[2]  = 0.48860251190291987f * z;
        d16[3]  = -0.48860251190291987f * x;
        d16[4]  = 1.0925484305920792f * x * y;
        d16[5]  = -1.0925484305920792f * y * z;
        d16[6]  = 0.94617469575756f * zz - 0.31539156525252f;
        d16[7]  = -1.0925484305920792f * x * z;
        d16[8]  = 0.5462742152960396f * (xx - yy);
        d16[9]  = 0.5900435899266435f * y * (3.0f * xx - yy);
        d16[10] = 2.890611442640554f * x * y * z;
        d16[11] = 0.4570457994644657f * y * (5.0f * zz - 1.0f);
        d16[12] = 0.37317633259011546f * z * (5.0f * zz - 3.0f);
        d16[13] = 0.4570457994644657f * x * (5.0f * zz - 1.0f);
        d16[14] = 1.445305721320277f * z * (xx - yy);
        d16[15] = 0.5900435899266435f * x * (xx - 3.0f * yy);
        float a = __ldg(&hb1g[j]);
#pragma unroll
        for (int i = 0; i < 16; i++) a = fmaf(d16[i], __ldg(&h1g[i * 64 + j]), a);
        sdc[g][j] = a;
    }

    // ---- stage enc (column-confined): levels l = tn*2+ll for own 8 columns ----
#pragma unroll
    for (int ll = 0; ll < 2; ll++) {
        int l = tn * 2 + ll;
        const float2* src = &g_enc[(size_t)l * NPTS + m0 + tm * 8];
        float2 e[8];
#pragma unroll
        for (int i = 0; i < 8; i++) e[i] = src[i];
#pragma unroll
        for (int i = 0; i < 8; i++) {
            s1[(2*l + 0) * SROW + tm * 8 + i] = e[i].x;
            s1[(2*l + 1) * SROW + tm * 8 + i] = e[i].y;
        }
    }
    __syncthreads();   // covers sdc (cross-warp) + staging

    float C[8][8];
    float A8[8], W8[8];

    // ---- GEMM1: enc(32 rows) -> hid(64 rows), relu, in-place ----
    {
        float4 bv0 = __ldg((const float4*)&b1g[tn * 8]);
        float4 bv1 = __ldg((const float4*)&b1g[tn * 8 + 4]);
        float bj[8] = {bv0.x, bv0.y, bv0.z, bv0.w, bv1.x, bv1.y, bv1.z, bv1.w};
#pragma unroll
        for (int j = 0; j < 8; j++)
#pragma unroll
            for (int i = 0; i < 8; i++) C[j][i] = bj[j];
#pragma unroll 4
        for (int k = 0; k < 32; k++) {
            float4 a0 = *(const float4*)&s1[k * SROW + tm * 8];
            float4 a1 = *(const float4*)&s1[k * SROW + tm * 8 + 4];
            A8[0]=a0.x; A8[1]=a0.y; A8[2]=a0.z; A8[3]=a0.w;
            A8[4]=a1.x; A8[5]=a1.y; A8[6]=a1.z; A8[7]=a1.w;
            float4 w0 = __ldg((const float4*)&w1g[k * 64 + tn * 8]);
            float4 w1v = __ldg((const float4*)&w1g[k * 64 + tn * 8 + 4]);
            W8[0]=w0.x; W8[1]=w0.y; W8[2]=w0.z; W8[3]=w0.w;
            W8[4]=w1v.x; W8[5]=w1v.y; W8[6]=w1v.z; W8[7]=w1v.w;
#pragma unroll
            for (int j = 0; j < 8; j++)
#pragma unroll
                for (int i = 0; i < 8; i++) C[j][i] = fmaf(W8[j], A8[i], C[j][i]);
        }
        __syncwarp();
#pragma unroll
        for (int j = 0; j < 8; j++) {
            int row = tn * 8 + j;
            *(float4*)&s1[row * SROW + tm * 8] = make_float4(
                fmaxf(C[j][0],0.f), fmaxf(C[j][1],0.f), fmaxf(C[j][2],0.f), fmaxf(C[j][3],0.f));
            *(float4*)&s1[row * SROW + tm * 8 + 4] = make_float4(
                fmaxf(C[j][4],0.f), fmaxf(C[j][5],0.f), fmaxf(C[j][6],0.f), fmaxf(C[j][7],0.f));
        }
        __syncwarp();
    }

    // ---- GEMM2: hid(64) -> geo(16 rows), relu, in-place rows 0..15 ----
    {
        float C2[2][8];
        float2 bv = __ldg((const float2*)&b2g[tn * 2]);
#pragma unroll
        for (int i = 0; i < 8; i++) { C2[0][i] = bv.x; C2[1][i] = bv.y; }
#pragma unroll 4
        for (int k = 0; k < 64; k++) {
            float4 a0 = *(const float4*)&s1[k * SROW + tm * 8];
            float4 a1 = *(const float4*)&s1[k * SROW + tm * 8 + 4];
            A8[0]=a0.x; A8[1]=a0.y; A8[2]=a0.z; A8[3]=a0.w;
            A8[4]=a1.x; A8[5]=a1.y; A8[6]=a1.z; A8[7]=a1.w;
            float2 w = __ldg((const float2*)&w2g[k * 16 + tn * 2]);
#pragma unroll
            for (int i = 0; i < 8; i++) {
                C2[0][i] = fmaf(w.x, A8[i], C2[0][i]);
                C2[1][i] = fmaf(w.y, A8[i], C2[1][i]);
            }
        }
        __syncwarp();
#pragma unroll
        for (int jj = 0; jj < 2; jj++) {
            int row = tn * 2 + jj;
            *(float4*)&s1[row * SROW + tm * 8] = make_float4(
                fmaxf(C2[jj][0],0.f), fmaxf(C2[jj][1],0.f), fmaxf(C2[jj][2],0.f), fmaxf(C2[jj][3],0.f));
            *(float4*)&s1[row * SROW + tm * 8 + 4] = make_float4(
                fmaxf(C2[jj][4],0.f), fmaxf(C2[jj][5],0.f), fmaxf(C2[jj][6],0.f), fmaxf(C2[jj][7],0.f));
        }
        __syncwarp();
    }

    // ---- GEMM3: geo(16) -> color hidden1 (64), init dc, relu, in-place ----
    {
        const int gl = tm / 6;   // batch of this m-tile (48 = 6 tiles of 8)
#pragma unroll
        for (int j = 0; j < 8; j++) {
            float dj = sdc[gl][tn * 8 + j];
#pragma unroll
            for (int i = 0; i < 8; i++) C[j][i] = dj;
        }
#pragma unroll 4
        for (int k = 0; k < 16; k++) {
            float4 a0 = *(const float4*)&s1[k * SROW + tm * 8];
            float4 a1 = *(const float4*)&s1[k * SROW + tm * 8 + 4];
            A8[0]=a0.x; A8[1]=a0.y; A8[2]=a0.z; A8[3]=a0.w;
            A8[4]=a1.x; A8[5]=a1.y; A8[6]=a1.z; A8[7]=a1.w;
            float4 w0 = __ldg((const float4*)&h1g[(16 + k) * 64 + tn * 8]);
            float4 w1v = __ldg((const float4*)&h1g[(16 + k) * 64 + tn * 8 + 4]);
            W8[0]=w0.x; W8[1]=w0.y; W8[2]=w0.z; W8[3]=w0.w;
            W8[4]=w1v.x; W8[5]=w1v.y; W8[6]=w1v.z; W8[7]=w1v.w;
#pragma unroll
            for (int j = 0; j < 8; j++)
#pragma unroll
                for (int i = 0; i < 8; i++) C[j][i] = fmaf(W8[j], A8[i], C[j][i]);
        }
        __syncwarp();
#pragma unroll
        for (int j = 0; j < 8; j++) {
            int row = tn * 8 + j;
            *(float4*)&s1[row * SROW + tm * 8] = make_float4(
                fmaxf(C[j][0],0.f), fmaxf(C[j][1],0.f), fmaxf(C[j][2],0.f), fmaxf(C[j][3],0.f));
            *(float4*)&s1[row * SROW + tm * 8 + 4] = make_float4(
                fmaxf(C[j][4],0.f), fmaxf(C[j][5],0.f), fmaxf(C[j][6],0.f), fmaxf(C[j][7],0.f));
        }
        __syncwarp();
    }

    // ---- GEMM4: hidden1(64) -> hidden2(64), +hb2, relu, in-place ----
    {
        float4 bv0 = __ldg((const float4*)&hb2g[tn * 8]);
        float4 bv1 = __ldg((const float4*)&hb2g[tn * 8 + 4]);
        float bj[8] = {bv0.x, bv0.y, bv0.z, bv0.w, bv1.x, bv1.y, bv1.z, bv1.w};
#pragma unroll
        for (int j = 0; j < 8; j++)
#pragma unroll
            for (int i = 0; i < 8; i++) C[j][i] = bj[j];
#pragma unroll 4
        for (int k = 0; k < 64; k++) {
            float4 a0 = *(const float4*)&s1[k * SROW + tm * 8];
            float4 a1 = *(const float4*)&s1[k * SROW + tm * 8 + 4];
            A8[0]=a0.x; A8[1]=a0.y; A8[2]=a0.z; A8[3]=a0.w;
            A8[4]=a1.x; A8[5]=a1.y; A8[6]=a1.z; A8[7]=a1.w;
            float4 w0 = __ldg((const float4*)&h2g[k * 64 + tn * 8]);
            float4 w1v = __ldg((const float4*)&h2g[k * 64 + tn * 8 + 4]);
            W8[0]=w0.x; W8[1]=w0.y; W8[2]=w0.z; W8[3]=w0.w;
            W8[4]=w1v.x; W8[5]=w1v.y; W8[6]=w1v.z; W8[7]=w1v.w;
#pragma unroll
            for (int j = 0; j < 8; j++)
#pragma unroll
                for (int i = 0; i < 8; i++) C[j][i] = fmaf(W8[j], A8[i], C[j][i]);
        }
        __syncwarp();
#pragma unroll
        for (int j = 0; j < 8; j++) {
            int row = tn * 8 + j;
            *(float4*)&s1[row * SROW + tm * 8] = make_float4(
                fmaxf(C[j][0],0.f), fmaxf(C[j][1],0.f), fmaxf(C[j][2],0.f), fmaxf(C[j][3],0.f));
            *(float4*)&s1[row * SROW + tm * 8 + 4] = make_float4(
                fmaxf(C[j][4],0.f), fmaxf(C[j][5],0.f), fmaxf(C[j][6],0.f), fmaxf(C[j][7],0.f));
        }
        __syncwarp();
    }

    // ---- final: hidden2 -> rgb(3), sigmoid; sample = tid (own column) ----
    {
        float r0 = __ldg(&hb3g[0]), r1 = __ldg(&hb3g[1]), r2 = __ldg(&hb3g[2]);
#pragma unroll 8
        for (int j = 0; j < 64; j++) {
            float t = s1[j * SROW + tid];
            r0 = fmaf(t, __ldg(&h3g[j*3+0]), r0);
            r1 = fmaf(t, __ldg(&h3g[j*3+1]), r1);
            r2 = fmaf(t, __ldg(&h3g[j*3+2]), r2);
        }
        r0 = 1.f / (1.f + expf(-r0));
        r1 = 1.f / (1.f + expf(-r1));
        r2 = 1.f / (1.f + expf(-r2));
        sden[tid] = densities[m0 + tid];
        srgb[tid][0] = r0; srgb[tid][1] = r1; srgb[tid][2] = r2;
    }
    __syncthreads();

    if ((tid % SPB) == 0) {
        const int g = tid / SPB;
        const float* dn = &sden[g * SPB];
        float mx = -1e30f;
        for (int k = 0; k < SPB; k++) mx = fmaxf(mx, dn[k]);
        float sum = 0.f, a0 = 0.f, a1 = 0.f, a2 = 0.f;
        for (int k = 0; k < SPB; k++) {
            float w = expf(dn[k] - mx);
            sum += w;
            a0 = fmaf(w, srgb[g*SPB+k][0], a0);
            a1 = fmaf(w, srgb[g*SPB+k][1], a1);
            a2 = fmaf(w, srgb[g*SPB+k][2], a2);
        }
        float inv = 1.f / sum;
        const int b = bb + g;
        out[b*3+0] = a0 * inv;
        out[b*3+1] = a1 * inv;
        out[b*3+2] = a2 * inv;
    }
}

// ---------------------------------------------------------------- launch
extern "C" void kernel_launch(void* const* d_in, const int* in_sizes, int n_in,
                              void* d_out, int out_size) {
    const float*  positions = (const float*)d_in[0];
    const float*  densities = (const float*)d_in[1];
    const float*  normals   = (const float*)d_in[2];
    const float*  c2w       = (const float*)d_in[3];
    const float2* table     = (const float2*)d_in[4];
    const float*  w1  = (const float*)d_in[5];
    const float*  b1  = (const float*)d_in[6];
    const float*  w2  = (const float*)d_in[7];
    const float*  b2  = (const float*)d_in[8];
    const float*  h1  = (const float*)d_in[9];
    const float*  hb1 = (const float*)d_in[10];
    const float*  h2  = (const float*)d_in[11];
    const float*  hb2 = (const float*)d_in[12];
    const float*  h3  = (const float*)d_in[13];
    const float*  hb3 = (const float*)d_in[14];
    float* out = (float*)d_out;

    const int B = in_sizes[2] / 3;        // 4096
    const int npts = B * SPB;             // 196608
    const int smem_b = 64 * SROW * (int)sizeof(float);  // 50176 B

    cudaFuncSetAttribute(mlp_kernel, cudaFuncAttributeMaxDynamicSharedMemorySize, smem_b);

    enc_kernel<<<npts / 256, 256>>>(positions, c2w, table);
    mlp_kernel<<<B / 4, 192, smem_b>>>(densities, normals, c2w,
                                       w1, b1, w2, b2, h1, hb1, h2, hb2, h3, hb3, out);
}